// round 10
// baseline (speedup 1.0000x reference)
#include <cuda_runtime.h>
#include <math.h>

typedef unsigned long long u64;

// Problem constants
#define B_   2
#define N_   2048
#define K_   48
#define KC_  24     // k-chunk
#define D0_  64
#define D1_  64
#define H_   64
#define EIN_ 193
#define E2_  386    // 2*EIN
#define H4_  256    // 4*H

__device__ int g_mask_mode;  // 0=uint8, 1=int32, 2=float32

// Pre-duplicated weight tables: each element is (w,w) packed as u64.
#define EW1P_N (129 * 386)
#define EW2P_N (386 * 64)
#define HW1P_N (64 * 256)
#define HW2P_N (256 * 64)
__device__ u64 g_eW1p[EW1P_N];  // rows 64..192 of eW1, [i][o]
__device__ u64 g_eW2p[EW2P_N];  // [o][h]
__device__ u64 g_hW1p[HW1P_N];  // [h][g]
__device__ u64 g_hW2p[HW2P_N];  // [g][d]

__global__ void detect_mask_kernel(const unsigned int* __restrict__ w) {
    bool int_ok = true, flt_ok = true;
    #pragma unroll 8
    for (int i = 0; i < 64; i++) {
        unsigned int v = w[i];
        if (v != 0u && v != 1u) int_ok = false;
        if (v != 0u && v != 0x3F800000u) flt_ok = false;
    }
    g_mask_mode = int_ok ? 1 : (flt_ok ? 2 : 0);
}

__device__ __forceinline__ u64 dup2(float w) {
    u64 r; asm("mov.b64 %0, {%1, %1};" : "=l"(r) : "f"(w)); return r;
}

__global__ __launch_bounds__(256) void prepack_kernel(
    const float* __restrict__ eW1, const float* __restrict__ eW2,
    const float* __restrict__ hW1, const float* __restrict__ hW2)
{
    int t = blockIdx.x * 256 + threadIdx.x;
    if (t < EW1P_N) {
        int i = t / 386, o = t % 386;
        g_eW1p[t] = dup2(eW1[(64 + i) * E2_ + o]);
        return;
    }
    t -= EW1P_N;
    if (t < EW2P_N) { g_eW2p[t] = dup2(eW2[t]); return; }
    t -= EW2P_N;
    if (t < HW1P_N) { g_hW1p[t] = dup2(hW1[t]); return; }
    t -= HW1P_N;
    if (t < HW2P_N) { g_hW2p[t] = dup2(hW2[t]); return; }
}

__device__ __forceinline__ float siluf(float v) {
    return v * __fdividef(1.f, 1.f + __expf(-v));
}
__device__ __forceinline__ void ffma2(u64 &d, u64 a, u64 b) {
    asm("fma.rn.f32x2 %0, %1, %2, %0;" : "+l"(d) : "l"(a), "l"(b));
}
__device__ __forceinline__ u64 addf2(u64 a, u64 b) {
    u64 r; asm("add.rn.f32x2 %0, %1, %2;" : "=l"(r) : "l"(a), "l"(b)); return r;
}
__device__ __forceinline__ float2 unpk(u64 v) {
    float2 f; asm("mov.b64 {%0, %1}, %2;" : "=f"(f.x), "=f"(f.y) : "l"(v)); return f;
}

// Shared memory layout (floats) -- chunked (KC=24)
#define OFF_NI   0          // 64
#define OFF_HTI  64         // 192
#define OFF_HNS  256        // 64
#define OFF_HNB  320        // 64
#define OFF_MSK  384        // 48
#define OFF_IDX  432        // 48 ints
#define OFF_MI   480        // 64
#define OFF_HTU  544        // 192
#define OFF_NM   736        // 128
#define OFF_HB   864        // 128
#define OFF_NO   992        // 64
#define OFF_STAT 1056       // 2
#define OFF_C0   1058       // 386
#define OFF_X    1448       // 129*24 = 3096   (reused as GEMM4 partial)
#define OFF_H1   4544       // 386*24 = 9264
#define OFF_M    13808      // 64*24 = 1536
#define OFF_H3   15344      // 256*24 = 6144   (first used as GEMM2 partials: 3*1536)
#define OFF_HTW  21488      // 64*24 = 1536
#define OFF_RED  23024      // 8*192 = 1536
#define SMEM_FLOATS 24560   // 98,240 bytes

__global__ __launch_bounds__(512, 2) void fused_kernel(
    const float* __restrict__ f0, const float* __restrict__ f1,
    const float* __restrict__ rd, const int* __restrict__ nidx,
    const unsigned char* __restrict__ nmask,
    const float* __restrict__ ln_g, const float* __restrict__ ln_b,
    const float* __restrict__ eW1, const float* __restrict__ eb1,
    const float* __restrict__ eb2,
    const float* __restrict__ hb1,
    const float* __restrict__ hb2,
    const float* __restrict__ nW1, const float* __restrict__ nb1,
    const float* __restrict__ nW2, const float* __restrict__ nb2,
    const float* __restrict__ hns, const float* __restrict__ hnb,
    const float* __restrict__ gW, const float* __restrict__ gb,
    float* __restrict__ out)
{
    extern __shared__ float sm[];
    const int node = blockIdx.x;
    const int base = (node >> 11) << 11;
    const int tid = threadIdx.x;

    float* ni_s  = sm + OFF_NI;
    float* hti   = sm + OFF_HTI;
    float* hns_s = sm + OFF_HNS;
    float* hnb_s = sm + OFF_HNB;
    float* msk_s = sm + OFF_MSK;
    int*   idx_s = (int*)(sm + OFF_IDX);
    float* mi_s  = sm + OFF_MI;
    float* htu_s = sm + OFF_HTU;
    float* nm    = sm + OFF_NM;
    float* hbuf  = sm + OFF_HB;
    float* no_s  = sm + OFF_NO;
    float* stat  = sm + OFF_STAT;
    float* c0_s  = sm + OFF_C0;
    float* x_s   = sm + OFF_X;
    float* h1_s  = sm + OFF_H1;
    float* m_s   = sm + OFF_M;
    float* h3_s  = sm + OFF_H3;
    float* htw_s = sm + OFF_HTW;
    float* red   = sm + OFF_RED;

    // ---- Stage 0: per-node loads ----
    if (tid < 64) {
        ni_s[tid]  = f0[node * 64 + tid];
        hns_s[tid] = hns[tid];
        hnb_s[tid] = hnb[tid];
        mi_s[tid]  = 0.f;
    }
    if (tid >= 64 && tid < 256) {
        hti[tid - 64] = f1[node * 192 + (tid - 64)];
        htu_s[tid - 64] = 0.f;
    }
    if (tid >= 256 && tid < 304) {
        int k = tid - 256;
        idx_s[k] = nidx[node * 48 + k];
        int mode = g_mask_mode;
        float mv;
        if (mode == 1)      mv = ((const int*)nmask)[node * 48 + k] ? 1.f : 0.f;
        else if (mode == 2) mv = ((const float*)nmask)[node * 48 + k];
        else                mv = nmask[node * 48 + k] ? 1.f : 0.f;
        msk_s[k] = mv;
    }
    __syncthreads();

    // ---- c0[o] = eb1[o] + nodes_i . eW1[0:64,o]  (once per block) ----
    if (tid < E2_) {
        float c = eb1[tid];
        #pragma unroll 8
        for (int i = 0; i < 64; i++) c += ni_s[i] * eW1[i * E2_ + tid];
        c0_s[tid] = c;
    }

    for (int c = 0; c < 2; c++) {
        const int kbase = c * KC_;

        // ---- Stage 1: build x rows for this chunk ----
        for (int e = tid; e < KC_ * 64; e += 512) {
            int k = e / 64, d = e % 64;
            int j = base + idx_s[kbase + k];
            x_s[d * KC_ + k] = f0[j * 64 + d];
            const float* hj = f1 + j * 192 + d * 3;
            float r0 = hti[d * 3 + 0] - hj[0];
            float r1 = hti[d * 3 + 1] - hj[1];
            float r2 = hti[d * 3 + 2] - hj[2];
            x_s[(64 + d) * KC_ + k] = sqrtf(r0 * r0 + r1 * r1 + r2 * r2);
        }
        if (tid < KC_) x_s[128 * KC_ + tid] = rd[node * 48 + kbase + tid];
        __syncthreads();

        // ---- GEMM1: h1[o][k] = silu( c0[o] + sum_i x[i][k]*eW1[64+i][o] ) ----
        {
            const int ob = tid & 127;
            const int k0 = (tid >> 7) * 6;
            const bool has4 = (ob < 2);

            u64 acc[3][3], acc4[3];
            #pragma unroll
            for (int oi = 0; oi < 3; oi++) {
                u64 d = dup2(c0_s[ob + oi * 128]);
                acc[oi][0] = d; acc[oi][1] = d; acc[oi][2] = d;
            }
            {
                u64 d = has4 ? dup2(c0_s[ob + 384]) : 0ull;
                acc4[0] = d; acc4[1] = d; acc4[2] = d;
            }

            const float* xb = x_s + k0;
            const u64* wbase = g_eW1p + ob;
            for (int i = 0; i < 129; i++) {
                const u64* xr = (const u64*)(xb + i * KC_);
                u64 a0 = xr[0], a1 = xr[1], a2 = xr[2];
                const u64* wr = wbase + i * 386;
                #pragma unroll
                for (int oi = 0; oi < 3; oi++) {
                    u64 w2 = wr[oi * 128];
                    ffma2(acc[oi][0], a0, w2);
                    ffma2(acc[oi][1], a1, w2);
                    ffma2(acc[oi][2], a2, w2);
                }
                if (has4) {
                    u64 w2 = wr[384];
                    ffma2(acc4[0], a0, w2);
                    ffma2(acc4[1], a1, w2);
                    ffma2(acc4[2], a2, w2);
                }
            }

            #pragma unroll
            for (int oi = 0; oi < 3; oi++) {
                float* dst = h1_s + (ob + oi * 128) * KC_ + k0;
                #pragma unroll
                for (int j = 0; j < 3; j++) {
                    float2 p = unpk(acc[oi][j]);
                    *(float2*)(dst + 2 * j) = make_float2(siluf(p.x), siluf(p.y));
                }
            }
            if (has4) {
                float* dst = h1_s + (ob + 384) * KC_ + k0;
                #pragma unroll
                for (int j = 0; j < 3; j++) {
                    float2 p = unpk(acc4[j]);
                    *(float2*)(dst + 2 * j) = make_float2(siluf(p.x), siluf(p.y));
                }
            }
        }
        __syncthreads();

        // ---- GEMM2: m[h][k] = silu( eb2[h] + sum_o h1[o][k]*eW2[o][h] ) ----
        // 4-way split over o: {0:97, 97:194, 194:290, 290:386}
        {
            const int oq = tid >> 7;
            const int h  = tid & 31;
            const int k0 = ((tid >> 5) & 3) * 6;
            const int o_start = (oq == 0) ? 0 : (oq == 1 ? 97 : (oq == 2 ? 194 : 290));
            const int o_end   = (oq == 0) ? 97 : (oq == 1 ? 194 : (oq == 2 ? 290 : 386));

            u64 acc[2][3];
            #pragma unroll
            for (int oi = 0; oi < 2; oi++) { acc[oi][0] = 0; acc[oi][1] = 0; acc[oi][2] = 0; }

            for (int o = o_start; o < o_end; o++) {
                const u64* hp = (const u64*)(h1_s + o * KC_ + k0);
                u64 a0 = hp[0], a1 = hp[1], a2 = hp[2];
                const u64* wr = g_eW2p + o * 64 + h;
                u64 w0 = wr[0], w1 = wr[32];
                ffma2(acc[0][0], a0, w0); ffma2(acc[0][1], a1, w0); ffma2(acc[0][2], a2, w0);
                ffma2(acc[1][0], a0, w1); ffma2(acc[1][1], a1, w1); ffma2(acc[1][2], a2, w1);
            }
            if (oq > 0) {
                float* part = h3_s + (oq - 1) * 1536;
                #pragma unroll
                for (int oi = 0; oi < 2; oi++)
                    #pragma unroll
                    for (int j = 0; j < 3; j++)
                        *(u64*)(part + (h + 32 * oi) * KC_ + k0 + 2 * j) = acc[oi][j];
            }
            __syncthreads();
            if (oq == 0) {
                #pragma unroll
                for (int oi = 0; oi < 2; oi++) {
                    int hh = h + 32 * oi;
                    u64 bpack = dup2(eb2[hh]);
                    #pragma unroll
                    for (int j = 0; j < 3; j++) {
                        u64 t = acc[oi][j];
                        t = addf2(t, *(u64*)(h3_s + 0 * 1536 + hh * KC_ + k0 + 2 * j));
                        t = addf2(t, *(u64*)(h3_s + 1 * 1536 + hh * KC_ + k0 + 2 * j));
                        t = addf2(t, *(u64*)(h3_s + 2 * 1536 + hh * KC_ + k0 + 2 * j));
                        t = addf2(t, bpack);
                        float2 p = unpk(t);
                        *(float2*)(m_s + hh * KC_ + k0 + 2 * j) = make_float2(siluf(p.x), siluf(p.y));
                    }
                }
            }
        }
        __syncthreads();

        // ---- GEMM3: h3[g][k] = silu( hb1[g] + sum_h m[h][k]*hW1[h][g] ) ----
        {
            const int g  = tid & 127;
            const int k0 = (tid >> 7) * 6;
            u64 acc[2][3];
            #pragma unroll
            for (int oi = 0; oi < 2; oi++) {
                u64 d = dup2(hb1[g + 128 * oi]);
                acc[oi][0] = d; acc[oi][1] = d; acc[oi][2] = d;
            }
            const u64* wbase = g_hW1p + g;
            #pragma unroll 2
            for (int h = 0; h < 64; h++) {
                const u64* mp = (const u64*)(m_s + h * KC_ + k0);
                u64 a0 = mp[0], a1 = mp[1], a2 = mp[2];
                const u64* wr = wbase + h * H4_;
                u64 w0 = wr[0], w1 = wr[128];
                ffma2(acc[0][0], a0, w0); ffma2(acc[0][1], a1, w0); ffma2(acc[0][2], a2, w0);
                ffma2(acc[1][0], a0, w1); ffma2(acc[1][1], a1, w1); ffma2(acc[1][2], a2, w1);
            }
            #pragma unroll
            for (int oi = 0; oi < 2; oi++) {
                float* dst = h3_s + (g + 128 * oi) * KC_ + k0;
                #pragma unroll
                for (int j = 0; j < 3; j++) {
                    float2 p = unpk(acc[oi][j]);
                    *(float2*)(dst + 2 * j) = make_float2(siluf(p.x), siluf(p.y));
                }
            }
        }
        __syncthreads();

        // ---- GEMM4: htw[d][k] = hb2[d] + sum_g h3[g][k]*hW2[g][d] ----
        {
            const int half = tid >> 8;
            const int d  = tid & 31;
            const int k0 = ((tid >> 5) & 3) * 6;
            const int g0 = half * 128;
            u64 acc[2][3];
            #pragma unroll
            for (int oi = 0; oi < 2; oi++) { acc[oi][0] = 0; acc[oi][1] = 0; acc[oi][2] = 0; }

            const u64* wbase = g_hW2p + d;
            #pragma unroll 2
            for (int g = g0; g < g0 + 128; g++) {
                const u64* hp = (const u64*)(h3_s + g * KC_ + k0);
                u64 a0 = hp[0], a1 = hp[1], a2 = hp[2];
                const u64* wr = wbase + g * 64;
                u64 w0 = wr[0], w1 = wr[32];
                ffma2(acc[0][0], a0, w0); ffma2(acc[0][1], a1, w0); ffma2(acc[0][2], a2, w0);
                ffma2(acc[1][0], a0, w1); ffma2(acc[1][1], a1, w1); ffma2(acc[1][2], a2, w1);
            }
            if (half == 0) {
                #pragma unroll
                for (int oi = 0; oi < 2; oi++)
                    #pragma unroll
                    for (int j = 0; j < 3; j++)
                        *(u64*)(x_s + (d + 32 * oi) * KC_ + k0 + 2 * j) = acc[oi][j];
            }
            __syncthreads();
            if (half == 1) {
                #pragma unroll
                for (int oi = 0; oi < 2; oi++) {
                    int dd = d + 32 * oi;
                    u64 bpack = dup2(hb2[dd]);
                    #pragma unroll
                    for (int j = 0; j < 3; j++) {
                        u64 t = addf2(addf2(acc[oi][j],
                                 *(u64*)(x_s + dd * KC_ + k0 + 2 * j)), bpack);
                        *(u64*)(htw_s + dd * KC_ + k0 + 2 * j) = t;
                    }
                }
            }
        }
        __syncthreads();

        // ---- m_i accumulation (masked sum over this chunk's k) ----
        {
            int h = tid & 63;
            int kb = tid >> 6;
            int k0 = kb * 3;
            float s = 0.f;
            #pragma unroll
            for (int kk = 0; kk < 3; kk++)
                s += msk_s[kbase + k0 + kk] * m_s[h * KC_ + k0 + kk];
            red[kb * 64 + h] = s;
        }
        __syncthreads();
        if (tid < 64) {
            float s = 0.f;
            #pragma unroll
            for (int kb = 0; kb < 8; kb++) s += red[kb * 64 + tid];
            mi_s[tid] += s;
        }
        __syncthreads();

        // ---- ht_update einsum for this chunk ----
        {
            int d = tid & 63;
            int kb = tid >> 6;
            int k0 = kb * 3;
            float a0 = 0.f, a1 = 0.f, a2 = 0.f;
            float sc = hns_s[d], bi = hnb_s[d];
            float h0 = hti[d * 3 + 0], h1v = hti[d * 3 + 1], h2 = hti[d * 3 + 2];
            #pragma unroll
            for (int kk = 0; kk < 3; kk++) {
                int k = k0 + kk;
                int j = base + idx_s[kbase + k];
                const float* hj = f1 + j * 192 + d * 3;
                float r0 = h0 - hj[0];
                float r1 = h1v - hj[1];
                float r2 = h2 - hj[2];
                float nrm = sqrtf(r0 * r0 + r1 * r1 + r2 * r2);
                float coef = (nrm * sc + bi) / fmaxf(nrm, 1e-8f);
                float w = coef * htw_s[d * KC_ + k];
                a0 += r0 * w; a1 += r1 * w; a2 += r2 * w;
            }
            red[kb * 192 + d * 3 + 0] = a0;
            red[kb * 192 + d * 3 + 1] = a1;
            red[kb * 192 + d * 3 + 2] = a2;
        }
        __syncthreads();
        if (tid < 192) {
            float s = 0.f;
            #pragma unroll
            for (int kb = 0; kb < 8; kb++) s += red[kb * 192 + tid];
            htu_s[tid] += s;
        }
        __syncthreads();
    }

    // ---- Node tail: LayerNorm -> MLP(128->128->64) + residual -> gate -> output ----
    if (tid < 32) {
        float s = ni_s[tid] + ni_s[tid + 32];
        #pragma unroll
        for (int off = 16; off > 0; off >>= 1) s += __shfl_xor_sync(0xffffffffu, s, off);
        if (tid == 0) stat[0] = s * (1.f / 64.f);
    }
    __syncthreads();
    if (tid < 32) {
        float mu = stat[0];
        float d0 = ni_s[tid] - mu, d1 = ni_s[tid + 32] - mu;
        float s = d0 * d0 + d1 * d1;
        #pragma unroll
        for (int off = 16; off > 0; off >>= 1) s += __shfl_xor_sync(0xffffffffu, s, off);
        if (tid == 0) stat[1] = s * (1.f / 64.f);
    }
    __syncthreads();
    if (tid < 64) {
        float mu = stat[0];
        float inv = rsqrtf(stat[1] + 1e-5f);
        nm[tid] = (ni_s[tid] - mu) * inv * ln_g[tid] + ln_b[tid];
        nm[64 + tid] = mi_s[tid];
    }
    __syncthreads();
    if (tid < 128) {
        float a = nb1[tid];
        #pragma unroll 8
        for (int e = 0; e < 128; e++) a += nm[e] * nW1[e * 128 + tid];
        hbuf[tid] = siluf(a);
    }
    __syncthreads();
    if (tid < 64) {
        float a = nb2[tid];
        #pragma unroll 8
        for (int g = 0; g < 128; g++) a += hbuf[g] * nW2[g * 64 + tid];
        no_s[tid] = a + ni_s[tid];
    }
    __syncthreads();
    if (tid < 64) {
        float a = gb[tid];
        #pragma unroll 8
        for (int e = 0; e < 64; e++) a += no_s[e] * gW[e * 64 + tid];
        float gate = __fdividef(1.f, 1.f + __expf(-a));
        int ob = node * 256 + tid * 4;
        out[ob + 0] = no_s[tid];
        #pragma unroll
        for (int m = 0; m < 3; m++)
            out[ob + 1 + m] = (hti[tid * 3 + m] + htu_s[tid * 3 + m]) * gate;
    }
}

extern "C" void kernel_launch(void* const* d_in, const int* in_sizes, int n_in,
                              void* d_out, int out_size)
{
    const float*         f0    = (const float*)d_in[0];
    const float*         f1    = (const float*)d_in[1];
    const float*         rd    = (const float*)d_in[2];
    const int*           nidx  = (const int*)d_in[3];
    const unsigned char* nmask = (const unsigned char*)d_in[4];
    const float* ln_g = (const float*)d_in[5];
    const float* ln_b = (const float*)d_in[6];
    const float* eW1  = (const float*)d_in[7];
    const float* eb1  = (const float*)d_in[8];
    const float* eW2  = (const float*)d_in[9];
    const float* eb2  = (const float*)d_in[10];
    const float* hW1  = (const float*)d_in[11];
    const float* hb1  = (const float*)d_in[12];
    const float* hW2  = (const float*)d_in[13];
    const float* hb2  = (const float*)d_in[14];
    const float* nW1  = (const float*)d_in[15];
    const float* nb1  = (const float*)d_in[16];
    const float* nW2  = (const float*)d_in[17];
    const float* nb2  = (const float*)d_in[18];
    const float* hns  = (const float*)d_in[19];
    const float* hnb  = (const float*)d_in[20];
    const float* gW   = (const float*)d_in[21];
    const float* gb   = (const float*)d_in[22];
    float* out = (float*)d_out;

    cudaFuncSetAttribute(fused_kernel, cudaFuncAttributeMaxDynamicSharedMemorySize,
                         SMEM_FLOATS * (int)sizeof(float));

    detect_mask_kernel<<<1, 1>>>((const unsigned int*)nmask);
    {
        int total = EW1P_N + EW2P_N + HW1P_N + HW2P_N;
        prepack_kernel<<<(total + 255) / 256, 256>>>(eW1, eW2, hW1, hW2);
    }
    fused_kernel<<<B_ * N_, 512, SMEM_FLOATS * sizeof(float)>>>(
        f0, f1, rd, nidx, nmask, ln_g, ln_b, eW1, eb1, eb2, hb1, hb2,
        nW1, nb1, nW2, nb2, hns, hnb, gW, gb, out);
}

// round 11
// speedup vs baseline: 1.2377x; 1.2377x over previous
#include <cuda_runtime.h>
#include <math.h>

typedef unsigned long long u64;

// Problem constants
#define B_   2
#define N_   2048
#define K_   48
#define KC_  24     // k-chunk
#define D0_  64
#define D1_  64
#define H_   64
#define EIN_ 193
#define E2_  386    // 2*EIN
#define H4_  256    // 4*H

__device__ int g_mask_mode;  // 0=uint8, 1=int32, 2=float32

__global__ void detect_mask_kernel(const unsigned int* __restrict__ w) {
    bool int_ok = true, flt_ok = true;
    #pragma unroll 8
    for (int i = 0; i < 64; i++) {
        unsigned int v = w[i];
        if (v != 0u && v != 1u) int_ok = false;
        if (v != 0u && v != 0x3F800000u) flt_ok = false;
    }
    g_mask_mode = int_ok ? 1 : (flt_ok ? 2 : 0);
}

__device__ __forceinline__ float siluf(float v) {
    return v * __fdividef(1.f, 1.f + __expf(-v));
}
__device__ __forceinline__ u64 dup2(float w) {
    u64 r; asm("mov.b64 %0, {%1, %1};" : "=l"(r) : "f"(w)); return r;
}
__device__ __forceinline__ void ffma2(u64 &d, u64 a, u64 b) {
    asm("fma.rn.f32x2 %0, %1, %2, %0;" : "+l"(d) : "l"(a), "l"(b));
}
__device__ __forceinline__ u64 addf2(u64 a, u64 b) {
    u64 r; asm("add.rn.f32x2 %0, %1, %2;" : "=l"(r) : "l"(a), "l"(b)); return r;
}
__device__ __forceinline__ float2 unpk(u64 v) {
    float2 f; asm("mov.b64 {%0, %1}, %2;" : "=f"(f.x), "=f"(f.y) : "l"(v)); return f;
}

// Shared memory layout (floats) -- chunked (KC=24), aggressively aliased.
// Aliases (verified against the barrier schedule):
//   red  -> x[0:1536]     (x rows 0-63 dead after GEMM1; GEMM4 partials in same
//                          region are consumed before the reduction phases)
//   htw  -> x[1536:3072]  (x rows 64-127 dead after GEMM1)
//   m    -> h1[0:1536]    (h1 rows 0-63 dead after GEMM2's internal barrier)
#define OFF_NI   0          // 64
#define OFF_HTI  64         // 192
#define OFF_HNS  256        // 64
#define OFF_HNB  320        // 64
#define OFF_MSK  384        // 48
#define OFF_IDX  432        // 48 ints
#define OFF_MI   480        // 64
#define OFF_HTU  544        // 192
#define OFF_NM   736        // 128
#define OFF_HB   864        // 128
#define OFF_NO   992        // 64
#define OFF_STAT 1056       // 2
#define OFF_C0   1058       // 386 (ends 1444)
#define OFF_X    1448       // 129*24+24 = 3120 region (rows + rel_dist row)
#define OFF_RED  1448       // alias: x[0:1536]
#define OFF_HTW  2984       // alias: x[1536:3072]
#define OFF_H1   4544       // 386*24 = 9264
#define OFF_M    4544       // alias: h1 rows 0-63 (1536 floats)
#define OFF_H3   13808      // 256*24 = 6144 (first used as GEMM2 partials 3*1536)
#define SMEM_FLOATS 19952   // 79,808 bytes -> 2 blocks/SM leaves ~68 KB L1D

__global__ __launch_bounds__(512, 2) void fused_kernel(
    const float* __restrict__ f0, const float* __restrict__ f1,
    const float* __restrict__ rd, const int* __restrict__ nidx,
    const unsigned char* __restrict__ nmask,
    const float* __restrict__ ln_g, const float* __restrict__ ln_b,
    const float* __restrict__ eW1, const float* __restrict__ eb1,
    const float* __restrict__ eW2, const float* __restrict__ eb2,
    const float* __restrict__ hW1, const float* __restrict__ hb1,
    const float* __restrict__ hW2, const float* __restrict__ hb2,
    const float* __restrict__ nW1, const float* __restrict__ nb1,
    const float* __restrict__ nW2, const float* __restrict__ nb2,
    const float* __restrict__ hns, const float* __restrict__ hnb,
    const float* __restrict__ gW, const float* __restrict__ gb,
    float* __restrict__ out)
{
    extern __shared__ float sm[];
    const int node = blockIdx.x;
    const int base = (node >> 11) << 11;
    const int tid = threadIdx.x;

    float* ni_s  = sm + OFF_NI;
    float* hti   = sm + OFF_HTI;
    float* hns_s = sm + OFF_HNS;
    float* hnb_s = sm + OFF_HNB;
    float* msk_s = sm + OFF_MSK;
    int*   idx_s = (int*)(sm + OFF_IDX);
    float* mi_s  = sm + OFF_MI;
    float* htu_s = sm + OFF_HTU;
    float* nm    = sm + OFF_NM;
    float* hbuf  = sm + OFF_HB;
    float* no_s  = sm + OFF_NO;
    float* stat  = sm + OFF_STAT;
    float* c0_s  = sm + OFF_C0;
    float* x_s   = sm + OFF_X;
    float* red   = sm + OFF_RED;
    float* htw_s = sm + OFF_HTW;
    float* h1_s  = sm + OFF_H1;
    float* m_s   = sm + OFF_M;
    float* h3_s  = sm + OFF_H3;

    // ---- Stage 0: per-node loads ----
    if (tid < 64) {
        ni_s[tid]  = f0[node * 64 + tid];
        hns_s[tid] = hns[tid];
        hnb_s[tid] = hnb[tid];
        mi_s[tid]  = 0.f;
    }
    if (tid >= 64 && tid < 256) {
        hti[tid - 64] = f1[node * 192 + (tid - 64)];
        htu_s[tid - 64] = 0.f;
    }
    if (tid >= 256 && tid < 304) {
        int k = tid - 256;
        idx_s[k] = nidx[node * 48 + k];
        int mode = g_mask_mode;
        float mv;
        if (mode == 1)      mv = ((const int*)nmask)[node * 48 + k] ? 1.f : 0.f;
        else if (mode == 2) mv = ((const float*)nmask)[node * 48 + k];
        else                mv = nmask[node * 48 + k] ? 1.f : 0.f;
        msk_s[k] = mv;
    }
    __syncthreads();

    // ---- c0[o] = eb1[o] + nodes_i . eW1[0:64,o]  (once per block) ----
    if (tid < E2_) {
        float c = eb1[tid];
        #pragma unroll 8
        for (int i = 0; i < 64; i++) c += ni_s[i] * eW1[i * E2_ + tid];
        c0_s[tid] = c;
    }

    for (int c = 0; c < 2; c++) {
        const int kbase = c * KC_;

        // ---- Stage 1: build x rows for this chunk ----
        for (int e = tid; e < KC_ * 64; e += 512) {
            int k = e / 64, d = e % 64;
            int j = base + idx_s[kbase + k];
            x_s[d * KC_ + k] = f0[j * 64 + d];
            const float* hj = f1 + j * 192 + d * 3;
            float r0 = hti[d * 3 + 0] - hj[0];
            float r1 = hti[d * 3 + 1] - hj[1];
            float r2 = hti[d * 3 + 2] - hj[2];
            x_s[(64 + d) * KC_ + k] = sqrtf(r0 * r0 + r1 * r1 + r2 * r2);
        }
        if (tid < KC_) x_s[128 * KC_ + tid] = rd[node * 48 + kbase + tid];
        __syncthreads();

        // ---- GEMM1: h1[o][k] = silu( c0[o] + sum_i x[i][k]*eW1[64+i][o] ) ----
        // ob in [0,128), 3(+1) outputs; kb in [0,4), 6 k each (3 packed).
        // Weights software-pipelined: next row prefetched into registers.
        {
            const int ob = tid & 127;
            const int k0 = (tid >> 7) * 6;
            const bool has4 = (ob < 2);

            u64 acc[3][3], acc4[3];
            #pragma unroll
            for (int oi = 0; oi < 3; oi++) {
                u64 d = dup2(c0_s[ob + oi * 128]);
                acc[oi][0] = d; acc[oi][1] = d; acc[oi][2] = d;
            }
            {
                u64 d = has4 ? dup2(c0_s[ob + 384]) : 0ull;
                acc4[0] = d; acc4[1] = d; acc4[2] = d;
            }

            const float* xb = x_s + k0;
            const float* wcol = eW1 + 64 * E2_ + ob;
            float wn0 = wcol[0], wn1 = wcol[128], wn2 = wcol[256];
            float wn3 = has4 ? wcol[384] : 0.f;
            for (int i = 0; i < 129; i++) {
                float w0 = wn0, w1 = wn1, w2v = wn2, w3 = wn3;
                if (i < 128) {
                    const float* wr = wcol + (i + 1) * E2_;
                    wn0 = wr[0]; wn1 = wr[128]; wn2 = wr[256];
                    if (has4) wn3 = wr[384];
                }
                const u64* xr = (const u64*)(xb + i * KC_);
                u64 a0 = xr[0], a1 = xr[1], a2 = xr[2];
                {
                    u64 wp = dup2(w0);
                    ffma2(acc[0][0], a0, wp); ffma2(acc[0][1], a1, wp); ffma2(acc[0][2], a2, wp);
                }
                {
                    u64 wp = dup2(w1);
                    ffma2(acc[1][0], a0, wp); ffma2(acc[1][1], a1, wp); ffma2(acc[1][2], a2, wp);
                }
                {
                    u64 wp = dup2(w2v);
                    ffma2(acc[2][0], a0, wp); ffma2(acc[2][1], a1, wp); ffma2(acc[2][2], a2, wp);
                }
                if (has4) {
                    u64 wp = dup2(w3);
                    ffma2(acc4[0], a0, wp); ffma2(acc4[1], a1, wp); ffma2(acc4[2], a2, wp);
                }
            }

            #pragma unroll
            for (int oi = 0; oi < 3; oi++) {
                float* dst = h1_s + (ob + oi * 128) * KC_ + k0;
                #pragma unroll
                for (int j = 0; j < 3; j++) {
                    float2 p = unpk(acc[oi][j]);
                    *(float2*)(dst + 2 * j) = make_float2(siluf(p.x), siluf(p.y));
                }
            }
            if (has4) {
                float* dst = h1_s + (ob + 384) * KC_ + k0;
                #pragma unroll
                for (int j = 0; j < 3; j++) {
                    float2 p = unpk(acc4[j]);
                    *(float2*)(dst + 2 * j) = make_float2(siluf(p.x), siluf(p.y));
                }
            }
        }
        __syncthreads();

        // ---- GEMM2: m[h][k] = silu( eb2[h] + sum_o h1[o][k]*eW2[o][h] ) ----
        // 4-way split over o: {0:97, 97:194, 194:290, 290:386}
        // NOTE: m_s aliases h1 rows 0-63; all h1 reads happen before the
        // internal barrier, all m writes after it.
        {
            const int oq = tid >> 7;
            const int h  = tid & 31;
            const int k0 = ((tid >> 5) & 3) * 6;
            const int o_start = (oq == 0) ? 0 : (oq == 1 ? 97 : (oq == 2 ? 194 : 290));
            const int o_end   = (oq == 0) ? 97 : (oq == 1 ? 194 : (oq == 2 ? 290 : 386));

            u64 acc[2][3];
            #pragma unroll
            for (int oi = 0; oi < 2; oi++) { acc[oi][0] = 0; acc[oi][1] = 0; acc[oi][2] = 0; }

            for (int o = o_start; o < o_end; o++) {
                const u64* hp = (const u64*)(h1_s + o * KC_ + k0);
                u64 a0 = hp[0], a1 = hp[1], a2 = hp[2];
                const float* wr = eW2 + o * 64 + h;
                u64 w0 = dup2(wr[0]), w1 = dup2(wr[32]);
                ffma2(acc[0][0], a0, w0); ffma2(acc[0][1], a1, w0); ffma2(acc[0][2], a2, w0);
                ffma2(acc[1][0], a0, w1); ffma2(acc[1][1], a1, w1); ffma2(acc[1][2], a2, w1);
            }
            if (oq > 0) {
                float* part = h3_s + (oq - 1) * 1536;
                #pragma unroll
                for (int oi = 0; oi < 2; oi++)
                    #pragma unroll
                    for (int j = 0; j < 3; j++)
                        *(u64*)(part + (h + 32 * oi) * KC_ + k0 + 2 * j) = acc[oi][j];
            }
            __syncthreads();
            if (oq == 0) {
                #pragma unroll
                for (int oi = 0; oi < 2; oi++) {
                    int hh = h + 32 * oi;
                    u64 bpack = dup2(eb2[hh]);
                    #pragma unroll
                    for (int j = 0; j < 3; j++) {
                        u64 t = acc[oi][j];
                        t = addf2(t, *(u64*)(h3_s + 0 * 1536 + hh * KC_ + k0 + 2 * j));
                        t = addf2(t, *(u64*)(h3_s + 1 * 1536 + hh * KC_ + k0 + 2 * j));
                        t = addf2(t, *(u64*)(h3_s + 2 * 1536 + hh * KC_ + k0 + 2 * j));
                        t = addf2(t, bpack);
                        float2 p = unpk(t);
                        *(float2*)(m_s + hh * KC_ + k0 + 2 * j) = make_float2(siluf(p.x), siluf(p.y));
                    }
                }
            }
        }
        __syncthreads();

        // ---- GEMM3: h3[g][k] = silu( hb1[g] + sum_h m[h][k]*hW1[h][g] ) ----
        {
            const int g  = tid & 127;
            const int k0 = (tid >> 7) * 6;
            u64 acc[2][3];
            #pragma unroll
            for (int oi = 0; oi < 2; oi++) {
                u64 d = dup2(hb1[g + 128 * oi]);
                acc[oi][0] = d; acc[oi][1] = d; acc[oi][2] = d;
            }
            #pragma unroll 2
            for (int h = 0; h < 64; h++) {
                const u64* mp = (const u64*)(m_s + h * KC_ + k0);
                u64 a0 = mp[0], a1 = mp[1], a2 = mp[2];
                const float* wr = hW1 + h * H4_ + g;
                u64 w0 = dup2(wr[0]), w1 = dup2(wr[128]);
                ffma2(acc[0][0], a0, w0); ffma2(acc[0][1], a1, w0); ffma2(acc[0][2], a2, w0);
                ffma2(acc[1][0], a0, w1); ffma2(acc[1][1], a1, w1); ffma2(acc[1][2], a2, w1);
            }
            #pragma unroll
            for (int oi = 0; oi < 2; oi++) {
                float* dst = h3_s + (g + 128 * oi) * KC_ + k0;
                #pragma unroll
                for (int j = 0; j < 3; j++) {
                    float2 p = unpk(acc[oi][j]);
                    *(float2*)(dst + 2 * j) = make_float2(siluf(p.x), siluf(p.y));
                }
            }
        }
        __syncthreads();

        // ---- GEMM4: htw[d][k] = hb2[d] + sum_g h3[g][k]*hW2[g][d] ----
        // Partials in x[0:1536]; htw aliases x[1536:3072] (x rows dead).
        {
            const int half = tid >> 8;
            const int d  = tid & 31;
            const int k0 = ((tid >> 5) & 3) * 6;
            const int g0 = half * 128;
            u64 acc[2][3];
            #pragma unroll
            for (int oi = 0; oi < 2; oi++) { acc[oi][0] = 0; acc[oi][1] = 0; acc[oi][2] = 0; }

            #pragma unroll 2
            for (int g = g0; g < g0 + 128; g++) {
                const u64* hp = (const u64*)(h3_s + g * KC_ + k0);
                u64 a0 = hp[0], a1 = hp[1], a2 = hp[2];
                const float* wr = hW2 + g * 64 + d;
                u64 w0 = dup2(wr[0]), w1 = dup2(wr[32]);
                ffma2(acc[0][0], a0, w0); ffma2(acc[0][1], a1, w0); ffma2(acc[0][2], a2, w0);
                ffma2(acc[1][0], a0, w1); ffma2(acc[1][1], a1, w1); ffma2(acc[1][2], a2, w1);
            }
            if (half == 0) {
                #pragma unroll
                for (int oi = 0; oi < 2; oi++)
                    #pragma unroll
                    for (int j = 0; j < 3; j++)
                        *(u64*)(x_s + (d + 32 * oi) * KC_ + k0 + 2 * j) = acc[oi][j];
            }
            __syncthreads();
            if (half == 1) {
                #pragma unroll
                for (int oi = 0; oi < 2; oi++) {
                    int dd = d + 32 * oi;
                    u64 bpack = dup2(hb2[dd]);
                    #pragma unroll
                    for (int j = 0; j < 3; j++) {
                        u64 t = addf2(addf2(acc[oi][j],
                                 *(u64*)(x_s + dd * KC_ + k0 + 2 * j)), bpack);
                        *(u64*)(htw_s + dd * KC_ + k0 + 2 * j) = t;
                    }
                }
            }
        }
        __syncthreads();

        // ---- m_i accumulation (masked sum over this chunk's k) ----
        {
            int h = tid & 63;
            int kb = tid >> 6;
            int k0 = kb * 3;
            float s = 0.f;
            #pragma unroll
            for (int kk = 0; kk < 3; kk++)
                s += msk_s[kbase + k0 + kk] * m_s[h * KC_ + k0 + kk];
            red[kb * 64 + h] = s;
        }
        __syncthreads();
        if (tid < 64) {
            float s = 0.f;
            #pragma unroll
            for (int kb = 0; kb < 8; kb++) s += red[kb * 64 + tid];
            mi_s[tid] += s;
        }
        __syncthreads();

        // ---- ht_update einsum for this chunk ----
        {
            int d = tid & 63;
            int kb = tid >> 6;
            int k0 = kb * 3;
            float a0 = 0.f, a1 = 0.f, a2 = 0.f;
            float sc = hns_s[d], bi = hnb_s[d];
            float h0 = hti[d * 3 + 0], h1v = hti[d * 3 + 1], h2 = hti[d * 3 + 2];
            #pragma unroll
            for (int kk = 0; kk < 3; kk++) {
                int k = k0 + kk;
                int j = base + idx_s[kbase + k];
                const float* hj = f1 + j * 192 + d * 3;
                float r0 = h0 - hj[0];
                float r1 = h1v - hj[1];
                float r2 = h2 - hj[2];
                float nrm = sqrtf(r0 * r0 + r1 * r1 + r2 * r2);
                float coef = (nrm * sc + bi) / fmaxf(nrm, 1e-8f);
                float w = coef * htw_s[d * KC_ + k];
                a0 += r0 * w; a1 += r1 * w; a2 += r2 * w;
            }
            red[kb * 192 + d * 3 + 0] = a0;
            red[kb * 192 + d * 3 + 1] = a1;
            red[kb * 192 + d * 3 + 2] = a2;
        }
        __syncthreads();
        if (tid < 192) {
            float s = 0.f;
            #pragma unroll
            for (int kb = 0; kb < 8; kb++) s += red[kb * 192 + tid];
            htu_s[tid] += s;
        }
        __syncthreads();
    }

    // ---- Node tail: LayerNorm -> MLP(128->128->64) + residual -> gate -> output ----
    if (tid < 32) {
        float s = ni_s[tid] + ni_s[tid + 32];
        #pragma unroll
        for (int off = 16; off > 0; off >>= 1) s += __shfl_xor_sync(0xffffffffu, s, off);
        if (tid == 0) stat[0] = s * (1.f / 64.f);
    }
    __syncthreads();
    if (tid < 32) {
        float mu = stat[0];
        float d0 = ni_s[tid] - mu, d1 = ni_s[tid + 32] - mu;
        float s = d0 * d0 + d1 * d1;
        #pragma unroll
        for (int off = 16; off > 0; off >>= 1) s += __shfl_xor_sync(0xffffffffu, s, off);
        if (tid == 0) stat[1] = s * (1.f / 64.f);
    }
    __syncthreads();
    if (tid < 64) {
        float mu = stat[0];
        float inv = rsqrtf(stat[1] + 1e-5f);
        nm[tid] = (ni_s[tid] - mu) * inv * ln_g[tid] + ln_b[tid];
        nm[64 + tid] = mi_s[tid];
    }
    __syncthreads();
    if (tid < 128) {
        float a = nb1[tid];
        #pragma unroll 8
        for (int e = 0; e < 128; e++) a += nm[e] * nW1[e * 128 + tid];
        hbuf[tid] = siluf(a);
    }
    __syncthreads();
    if (tid < 64) {
        float a = nb2[tid];
        #pragma unroll 8
        for (int g = 0; g < 128; g++) a += hbuf[g] * nW2[g * 64 + tid];
        no_s[tid] = a + ni_s[tid];
    }
    __syncthreads();
    if (tid < 64) {
        float a = gb[tid];
        #pragma unroll 8
        for (int e = 0; e < 64; e++) a += no_s[e] * gW[e * 64 + tid];
        float gate = __fdividef(1.f, 1.f + __expf(-a));
        int ob = node * 256 + tid * 4;
        out[ob + 0] = no_s[tid];
        #pragma unroll
        for (int m = 0; m < 3; m++)
            out[ob + 1 + m] = (hti[tid * 3 + m] + htu_s[tid * 3 + m]) * gate;
    }
}

extern "C" void kernel_launch(void* const* d_in, const int* in_sizes, int n_in,
                              void* d_out, int out_size)
{
    const float*         f0    = (const float*)d_in[0];
    const float*         f1    = (const float*)d_in[1];
    const float*         rd    = (const float*)d_in[2];
    const int*           nidx  = (const int*)d_in[3];
    const unsigned char* nmask = (const unsigned char*)d_in[4];
    const float* ln_g = (const float*)d_in[5];
    const float* ln_b = (const float*)d_in[6];
    const float* eW1  = (const float*)d_in[7];
    const float* eb1  = (const float*)d_in[8];
    const float* eW2  = (const float*)d_in[9];
    const float* eb2  = (const float*)d_in[10];
    const float* hW1  = (const float*)d_in[11];
    const float* hb1  = (const float*)d_in[12];
    const float* hW2  = (const float*)d_in[13];
    const float* hb2  = (const float*)d_in[14];
    const float* nW1  = (const float*)d_in[15];
    const float* nb1  = (const float*)d_in[16];
    const float* nW2  = (const float*)d_in[17];
    const float* nb2  = (const float*)d_in[18];
    const float* hns  = (const float*)d_in[19];
    const float* hnb  = (const float*)d_in[20];
    const float* gW   = (const float*)d_in[21];
    const float* gb   = (const float*)d_in[22];
    float* out = (float*)d_out;

    cudaFuncSetAttribute(fused_kernel, cudaFuncAttributeMaxDynamicSharedMemorySize,
                         SMEM_FLOATS * (int)sizeof(float));

    detect_mask_kernel<<<1, 1>>>((const unsigned int*)nmask);
    fused_kernel<<<B_ * N_, 512, SMEM_FLOATS * sizeof(float)>>>(
        f0, f1, rd, nidx, nmask, ln_g, ln_b, eW1, eb1, eW2, eb2, hW1, hb1, hW2, hb2,
        nW1, nb1, nW2, nb2, hns, hnb, gW, gb, out);
}

// round 12
// speedup vs baseline: 1.4494x; 1.1711x over previous
#include <cuda_runtime.h>
#include <math.h>

typedef unsigned long long u64;

// Problem constants
#define B_   2
#define N_   2048
#define K_   48
#define KC_  24     // k-chunk
#define D0_  64
#define D1_  64
#define H_   64
#define EIN_ 193
#define E2_  386    // 2*EIN
#define H4_  256    // 4*H

__device__ int g_mask_mode;  // 0=uint8, 1=int32, 2=float32

// Per-node rank-0 tables for GEMM1:
//   g_c0[n][o] = eb1[o] + nodes[n] . eW1[0:64, o]    (i-role)
//   g_c1[n][o] =          nodes[n] . eW1[64:128, o]  (j-role)
__device__ float g_c0[B_ * N_ * E2_];   // 6.05 MB
__device__ float g_c1[B_ * N_ * E2_];   // 6.05 MB

__global__ void detect_mask_kernel(const unsigned int* __restrict__ w) {
    bool int_ok = true, flt_ok = true;
    #pragma unroll 8
    for (int i = 0; i < 64; i++) {
        unsigned int v = w[i];
        if (v != 0u && v != 1u) int_ok = false;
        if (v != 0u && v != 0x3F800000u) flt_ok = false;
    }
    g_mask_mode = int_ok ? 1 : (flt_ok ? 2 : 0);
}

// Precompute c0/c1 for all nodes. Grid 32 x 512: block handles 128 nodes.
__global__ __launch_bounds__(512) void c01_kernel(
    const float* __restrict__ f0, const float* __restrict__ eW1,
    const float* __restrict__ eb1)
{
    __shared__ float f0s[128 * 64];   // 32 KB
    const int n0 = blockIdx.x * 128;
    const int tid = threadIdx.x;
    for (int e = tid; e < 128 * 64; e += 512) f0s[e] = f0[n0 * 64 + e];
    __syncthreads();
    const int o = tid;
    if (o < E2_) {
        float b = eb1[o];
        for (int g = 0; g < 8; g++) {
            float c0a[16], c1a[16];
            #pragma unroll
            for (int nn = 0; nn < 16; nn++) { c0a[nn] = 0.f; c1a[nn] = 0.f; }
            const float* fg = f0s + g * 16 * 64;
            for (int d = 0; d < 64; d++) {
                float w0 = eW1[d * E2_ + o];
                float w1 = eW1[(64 + d) * E2_ + o];
                #pragma unroll
                for (int nn = 0; nn < 16; nn++) {
                    float f = fg[nn * 64 + d];
                    c0a[nn] += f * w0;
                    c1a[nn] += f * w1;
                }
            }
            #pragma unroll
            for (int nn = 0; nn < 16; nn++) {
                int n = n0 + g * 16 + nn;
                g_c0[(u64)n * E2_ + o] = c0a[nn] + b;
                g_c1[(u64)n * E2_ + o] = c1a[nn];
            }
        }
    }
}

__device__ __forceinline__ float siluf(float v) {
    return v * __fdividef(1.f, 1.f + __expf(-v));
}
__device__ __forceinline__ u64 dup2(float w) {
    u64 r; asm("mov.b64 %0, {%1, %1};" : "=l"(r) : "f"(w)); return r;
}
__device__ __forceinline__ void ffma2(u64 &d, u64 a, u64 b) {
    asm("fma.rn.f32x2 %0, %1, %2, %0;" : "+l"(d) : "l"(a), "l"(b));
}
__device__ __forceinline__ u64 addf2(u64 a, u64 b) {
    u64 r; asm("add.rn.f32x2 %0, %1, %2;" : "=l"(r) : "l"(a), "l"(b)); return r;
}
__device__ __forceinline__ float2 unpk(u64 v) {
    float2 f; asm("mov.b64 {%0, %1}, %2;" : "=f"(f.x), "=f"(f.y) : "l"(v)); return f;
}

// Shared memory layout (floats) -- chunked (KC=24), aliased.
//   x:   65 rows x 24  (relhtdist 64 rows + reldist row) -- dead after GEMM1
//   red -> x[0:1536]      (also GEMM4 partials; consumed before reductions)
//   htw : own region
//   m   -> h1 rows 0..63  (h1 dead after GEMM2 internal barrier)
#define OFF_NI   0          // 64
#define OFF_HTI  64         // 192
#define OFF_HNS  256        // 64
#define OFF_HNB  320        // 64
#define OFF_MSK  384        // 48
#define OFF_IDX  432        // 48 ints
#define OFF_MI   480        // 64
#define OFF_HTU  544        // 192
#define OFF_NM   736        // 128
#define OFF_HB   864        // 128
#define OFF_NO   992        // 64
#define OFF_STAT 1056       // 2
#define OFF_C0   1058       // 386 (ends 1444)
#define OFF_X    1448       // 65*24 = 1560
#define OFF_RED  1448       // alias: x[0:1536]
#define OFF_HTW  3032       // 64*24 = 1536
#define OFF_H1   4568       // 386*24 = 9264
#define OFF_M    4568       // alias: h1 rows 0-63 (1536 floats)
#define OFF_H3   13832      // 256*24 = 6144 (first used as GEMM2 partials 3*1536)
#define SMEM_FLOATS 19976   // 79,904 bytes -> 2 blocks/SM

__global__ __launch_bounds__(512, 2) void fused_kernel(
    const float* __restrict__ f0, const float* __restrict__ f1,
    const float* __restrict__ rd, const int* __restrict__ nidx,
    const unsigned char* __restrict__ nmask,
    const float* __restrict__ ln_g, const float* __restrict__ ln_b,
    const float* __restrict__ eW1,
    const float* __restrict__ eW2, const float* __restrict__ eb2,
    const float* __restrict__ hW1, const float* __restrict__ hb1,
    const float* __restrict__ hW2, const float* __restrict__ hb2,
    const float* __restrict__ nW1, const float* __restrict__ nb1,
    const float* __restrict__ nW2, const float* __restrict__ nb2,
    const float* __restrict__ hns, const float* __restrict__ hnb,
    const float* __restrict__ gW, const float* __restrict__ gb,
    float* __restrict__ out)
{
    extern __shared__ float sm[];
    const int node = blockIdx.x;
    const int base = (node >> 11) << 11;
    const int tid = threadIdx.x;

    float* ni_s  = sm + OFF_NI;
    float* hti   = sm + OFF_HTI;
    float* hns_s = sm + OFF_HNS;
    float* hnb_s = sm + OFF_HNB;
    float* msk_s = sm + OFF_MSK;
    int*   idx_s = (int*)(sm + OFF_IDX);
    float* mi_s  = sm + OFF_MI;
    float* htu_s = sm + OFF_HTU;
    float* nm    = sm + OFF_NM;
    float* hbuf  = sm + OFF_HB;
    float* no_s  = sm + OFF_NO;
    float* stat  = sm + OFF_STAT;
    float* c0_s  = sm + OFF_C0;
    float* x_s   = sm + OFF_X;
    float* red   = sm + OFF_RED;
    float* htw_s = sm + OFF_HTW;
    float* h1_s  = sm + OFF_H1;
    float* m_s   = sm + OFF_M;
    float* h3_s  = sm + OFF_H3;

    // ---- Stage 0: per-node loads ----
    if (tid < 64) {
        ni_s[tid]  = f0[node * 64 + tid];
        hns_s[tid] = hns[tid];
        hnb_s[tid] = hnb[tid];
        mi_s[tid]  = 0.f;
    }
    if (tid >= 64 && tid < 256) {
        hti[tid - 64] = f1[node * 192 + (tid - 64)];
        htu_s[tid - 64] = 0.f;
    }
    if (tid >= 256 && tid < 304) {
        int k = tid - 256;
        idx_s[k] = nidx[node * 48 + k];
        int mode = g_mask_mode;
        float mv;
        if (mode == 1)      mv = ((const int*)nmask)[node * 48 + k] ? 1.f : 0.f;
        else if (mode == 2) mv = ((const float*)nmask)[node * 48 + k];
        else                mv = nmask[node * 48 + k] ? 1.f : 0.f;
        msk_s[k] = mv;
    }
    // c0 table load (replaces per-block recompute)
    if (tid < E2_) c0_s[tid] = g_c0[(u64)node * E2_ + tid];
    __syncthreads();

    for (int c = 0; c < 2; c++) {
        const int kbase = c * KC_;

        // ---- Stage 1: build x rows (rel_ht_dist only) for this chunk ----
        for (int e = tid; e < KC_ * 64; e += 512) {
            int k = e / 64, d = e % 64;
            int j = base + idx_s[kbase + k];
            const float* hj = f1 + j * 192 + d * 3;
            float r0 = hti[d * 3 + 0] - hj[0];
            float r1 = hti[d * 3 + 1] - hj[1];
            float r2 = hti[d * 3 + 2] - hj[2];
            x_s[d * KC_ + k] = sqrtf(r0 * r0 + r1 * r1 + r2 * r2);
        }
        if (tid < KC_) x_s[64 * KC_ + tid] = rd[node * 48 + kbase + tid];
        __syncthreads();

        // ---- GEMM1: h1[o][k] = silu( c0_i[o] + c1_j[o] + sum_i x[i][k]*eW1[128+i][o] ) ----
        // ob in [0,128), 3(+1) outputs; kb in [0,4), 6 k each (3 packed).
        {
            const int ob = tid & 127;
            const int k0 = (tid >> 7) * 6;
            const bool has4 = (ob < 2);

            u64 acc[3][3], acc4[3];
            #pragma unroll
            for (int oi = 0; oi < 3; oi++) {
                u64 d = dup2(c0_s[ob + oi * 128]);
                acc[oi][0] = d; acc[oi][1] = d; acc[oi][2] = d;
            }
            {
                u64 d = has4 ? dup2(c0_s[ob + 384]) : 0ull;
                acc4[0] = d; acc4[1] = d; acc4[2] = d;
            }

            const float* xb = x_s + k0;
            const float* wcol = eW1 + 128 * E2_ + ob;   // rows 128..192
            float wn0 = wcol[0], wn1 = wcol[128], wn2 = wcol[256];
            float wn3 = has4 ? wcol[384] : 0.f;
            for (int i = 0; i < 65; i++) {
                float w0 = wn0, w1 = wn1, w2v = wn2, w3 = wn3;
                if (i < 64) {
                    const float* wr = wcol + (i + 1) * E2_;
                    wn0 = wr[0]; wn1 = wr[128]; wn2 = wr[256];
                    if (has4) wn3 = wr[384];
                }
                const u64* xr = (const u64*)(xb + i * KC_);
                u64 a0 = xr[0], a1 = xr[1], a2 = xr[2];
                {
                    u64 wp = dup2(w0);
                    ffma2(acc[0][0], a0, wp); ffma2(acc[0][1], a1, wp); ffma2(acc[0][2], a2, wp);
                }
                {
                    u64 wp = dup2(w1);
                    ffma2(acc[1][0], a0, wp); ffma2(acc[1][1], a1, wp); ffma2(acc[1][2], a2, wp);
                }
                {
                    u64 wp = dup2(w2v);
                    ffma2(acc[2][0], a0, wp); ffma2(acc[2][1], a1, wp); ffma2(acc[2][2], a2, wp);
                }
                if (has4) {
                    u64 wp = dup2(w3);
                    ffma2(acc4[0], a0, wp); ffma2(acc4[1], a1, wp); ffma2(acc4[2], a2, wp);
                }
            }

            // epilogue: add gathered c1_j, silu, store
            const float* c1p[6];
            #pragma unroll
            for (int jj = 0; jj < 6; jj++)
                c1p[jj] = g_c1 + (u64)(base + idx_s[kbase + k0 + jj]) * E2_;

            #pragma unroll
            for (int oi = 0; oi < 3; oi++) {
                int o = ob + oi * 128;
                float* dst = h1_s + o * KC_ + k0;
                #pragma unroll
                for (int j2 = 0; j2 < 3; j2++) {
                    float2 p = unpk(acc[oi][j2]);
                    p.x = siluf(p.x + c1p[2 * j2][o]);
                    p.y = siluf(p.y + c1p[2 * j2 + 1][o]);
                    *(float2*)(dst + 2 * j2) = p;
                }
            }
            if (has4) {
                int o = ob + 384;
                float* dst = h1_s + o * KC_ + k0;
                #pragma unroll
                for (int j2 = 0; j2 < 3; j2++) {
                    float2 p = unpk(acc4[j2]);
                    p.x = siluf(p.x + c1p[2 * j2][o]);
                    p.y = siluf(p.y + c1p[2 * j2 + 1][o]);
                    *(float2*)(dst + 2 * j2) = p;
                }
            }
        }
        __syncthreads();

        // ---- GEMM2: m[h][k] = silu( eb2[h] + sum_o h1[o][k]*eW2[o][h] ) ----
        // 4-way split over o: {0:97, 97:194, 194:290, 290:386}
        {
            const int oq = tid >> 7;
            const int h  = tid & 31;
            const int k0 = ((tid >> 5) & 3) * 6;
            const int o_start = (oq == 0) ? 0 : (oq == 1 ? 97 : (oq == 2 ? 194 : 290));
            const int o_end   = (oq == 0) ? 97 : (oq == 1 ? 194 : (oq == 2 ? 290 : 386));

            u64 acc[2][3];
            #pragma unroll
            for (int oi = 0; oi < 2; oi++) { acc[oi][0] = 0; acc[oi][1] = 0; acc[oi][2] = 0; }

            for (int o = o_start; o < o_end; o++) {
                const u64* hp = (const u64*)(h1_s + o * KC_ + k0);
                u64 a0 = hp[0], a1 = hp[1], a2 = hp[2];
                const float* wr = eW2 + o * 64 + h;
                u64 w0 = dup2(wr[0]), w1 = dup2(wr[32]);
                ffma2(acc[0][0], a0, w0); ffma2(acc[0][1], a1, w0); ffma2(acc[0][2], a2, w0);
                ffma2(acc[1][0], a0, w1); ffma2(acc[1][1], a1, w1); ffma2(acc[1][2], a2, w1);
            }
            if (oq > 0) {
                float* part = h3_s + (oq - 1) * 1536;
                #pragma unroll
                for (int oi = 0; oi < 2; oi++)
                    #pragma unroll
                    for (int j = 0; j < 3; j++)
                        *(u64*)(part + (h + 32 * oi) * KC_ + k0 + 2 * j) = acc[oi][j];
            }
            __syncthreads();
            if (oq == 0) {
                #pragma unroll
                for (int oi = 0; oi < 2; oi++) {
                    int hh = h + 32 * oi;
                    u64 bpack = dup2(eb2[hh]);
                    #pragma unroll
                    for (int j = 0; j < 3; j++) {
                        u64 t = acc[oi][j];
                        t = addf2(t, *(u64*)(h3_s + 0 * 1536 + hh * KC_ + k0 + 2 * j));
                        t = addf2(t, *(u64*)(h3_s + 1 * 1536 + hh * KC_ + k0 + 2 * j));
                        t = addf2(t, *(u64*)(h3_s + 2 * 1536 + hh * KC_ + k0 + 2 * j));
                        t = addf2(t, bpack);
                        float2 p = unpk(t);
                        *(float2*)(m_s + hh * KC_ + k0 + 2 * j) = make_float2(siluf(p.x), siluf(p.y));
                    }
                }
            }
        }
        __syncthreads();

        // ---- GEMM3: h3[g][k] = silu( hb1[g] + sum_h m[h][k]*hW1[h][g] ) ----
        {
            const int g  = tid & 127;
            const int k0 = (tid >> 7) * 6;
            u64 acc[2][3];
            #pragma unroll
            for (int oi = 0; oi < 2; oi++) {
                u64 d = dup2(hb1[g + 128 * oi]);
                acc[oi][0] = d; acc[oi][1] = d; acc[oi][2] = d;
            }
            #pragma unroll 2
            for (int h = 0; h < 64; h++) {
                const u64* mp = (const u64*)(m_s + h * KC_ + k0);
                u64 a0 = mp[0], a1 = mp[1], a2 = mp[2];
                const float* wr = hW1 + h * H4_ + g;
                u64 w0 = dup2(wr[0]), w1 = dup2(wr[128]);
                ffma2(acc[0][0], a0, w0); ffma2(acc[0][1], a1, w0); ffma2(acc[0][2], a2, w0);
                ffma2(acc[1][0], a0, w1); ffma2(acc[1][1], a1, w1); ffma2(acc[1][2], a2, w1);
            }
            #pragma unroll
            for (int oi = 0; oi < 2; oi++) {
                float* dst = h3_s + (g + 128 * oi) * KC_ + k0;
                #pragma unroll
                for (int j = 0; j < 3; j++) {
                    float2 p = unpk(acc[oi][j]);
                    *(float2*)(dst + 2 * j) = make_float2(siluf(p.x), siluf(p.y));
                }
            }
        }
        __syncthreads();

        // ---- GEMM4: htw[d][k] = hb2[d] + sum_g h3[g][k]*hW2[g][d] ----
        {
            const int half = tid >> 8;
            const int d  = tid & 31;
            const int k0 = ((tid >> 5) & 3) * 6;
            const int g0 = half * 128;
            u64 acc[2][3];
            #pragma unroll
            for (int oi = 0; oi < 2; oi++) { acc[oi][0] = 0; acc[oi][1] = 0; acc[oi][2] = 0; }

            #pragma unroll 2
            for (int g = g0; g < g0 + 128; g++) {
                const u64* hp = (const u64*)(h3_s + g * KC_ + k0);
                u64 a0 = hp[0], a1 = hp[1], a2 = hp[2];
                const float* wr = hW2 + g * 64 + d;
                u64 w0 = dup2(wr[0]), w1 = dup2(wr[32]);
                ffma2(acc[0][0], a0, w0); ffma2(acc[0][1], a1, w0); ffma2(acc[0][2], a2, w0);
                ffma2(acc[1][0], a0, w1); ffma2(acc[1][1], a1, w1); ffma2(acc[1][2], a2, w1);
            }
            if (half == 0) {
                #pragma unroll
                for (int oi = 0; oi < 2; oi++)
                    #pragma unroll
                    for (int j = 0; j < 3; j++)
                        *(u64*)(x_s + (d + 32 * oi) * KC_ + k0 + 2 * j) = acc[oi][j];
            }
            __syncthreads();
            if (half == 1) {
                #pragma unroll
                for (int oi = 0; oi < 2; oi++) {
                    int dd = d + 32 * oi;
                    u64 bpack = dup2(hb2[dd]);
                    #pragma unroll
                    for (int j = 0; j < 3; j++) {
                        u64 t = addf2(addf2(acc[oi][j],
                                 *(u64*)(x_s + dd * KC_ + k0 + 2 * j)), bpack);
                        *(u64*)(htw_s + dd * KC_ + k0 + 2 * j) = t;
                    }
                }
            }
        }
        __syncthreads();

        // ---- m_i accumulation (masked sum over this chunk's k) ----
        {
            int h = tid & 63;
            int kb = tid >> 6;
            int k0 = kb * 3;
            float s = 0.f;
            #pragma unroll
            for (int kk = 0; kk < 3; kk++)
                s += msk_s[kbase + k0 + kk] * m_s[h * KC_ + k0 + kk];
            red[kb * 64 + h] = s;
        }
        __syncthreads();
        if (tid < 64) {
            float s = 0.f;
            #pragma unroll
            for (int kb = 0; kb < 8; kb++) s += red[kb * 64 + tid];
            mi_s[tid] += s;
        }
        __syncthreads();

        // ---- ht_update einsum for this chunk ----
        {
            int d = tid & 63;
            int kb = tid >> 6;
            int k0 = kb * 3;
            float a0 = 0.f, a1 = 0.f, a2 = 0.f;
            float sc = hns_s[d], bi = hnb_s[d];
            float h0 = hti[d * 3 + 0], h1v = hti[d * 3 + 1], h2 = hti[d * 3 + 2];
            #pragma unroll
            for (int kk = 0; kk < 3; kk++) {
                int k = k0 + kk;
                int j = base + idx_s[kbase + k];
                const float* hj = f1 + j * 192 + d * 3;
                float r0 = h0 - hj[0];
                float r1 = h1v - hj[1];
                float r2 = h2 - hj[2];
                float nrm = sqrtf(r0 * r0 + r1 * r1 + r2 * r2);
                float coef = (nrm * sc + bi) / fmaxf(nrm, 1e-8f);
                float w = coef * htw_s[d * KC_ + k];
                a0 += r0 * w; a1 += r1 * w; a2 += r2 * w;
            }
            red[kb * 192 + d * 3 + 0] = a0;
            red[kb * 192 + d * 3 + 1] = a1;
            red[kb * 192 + d * 3 + 2] = a2;
        }
        __syncthreads();
        if (tid < 192) {
            float s = 0.f;
            #pragma unroll
            for (int kb = 0; kb < 8; kb++) s += red[kb * 192 + tid];
            htu_s[tid] += s;
        }
        __syncthreads();
    }

    // ---- Node tail: LayerNorm -> MLP(128->128->64) + residual -> gate -> output ----
    if (tid < 32) {
        float s = ni_s[tid] + ni_s[tid + 32];
        #pragma unroll
        for (int off = 16; off > 0; off >>= 1) s += __shfl_xor_sync(0xffffffffu, s, off);
        if (tid == 0) stat[0] = s * (1.f / 64.f);
    }
    __syncthreads();
    if (tid < 32) {
        float mu = stat[0];
        float d0 = ni_s[tid] - mu, d1 = ni_s[tid + 32] - mu;
        float s = d0 * d0 + d1 * d1;
        #pragma unroll
        for (int off = 16; off > 0; off >>= 1) s += __shfl_xor_sync(0xffffffffu, s, off);
        if (tid == 0) stat[1] = s * (1.f / 64.f);
    }
    __syncthreads();
    if (tid < 64) {
        float mu = stat[0];
        float inv = rsqrtf(stat[1] + 1e-5f);
        nm[tid] = (ni_s[tid] - mu) * inv * ln_g[tid] + ln_b[tid];
        nm[64 + tid] = mi_s[tid];
    }
    __syncthreads();
    if (tid < 128) {
        float a = nb1[tid];
        #pragma unroll 8
        for (int e = 0; e < 128; e++) a += nm[e] * nW1[e * 128 + tid];
        hbuf[tid] = siluf(a);
    }
    __syncthreads();
    if (tid < 64) {
        float a = nb2[tid];
        #pragma unroll 8
        for (int g = 0; g < 128; g++) a += hbuf[g] * nW2[g * 64 + tid];
        no_s[tid] = a + ni_s[tid];
    }
    __syncthreads();
    if (tid < 64) {
        float a = gb[tid];
        #pragma unroll 8
        for (int e = 0; e < 64; e++) a += no_s[e] * gW[e * 64 + tid];
        float gate = __fdividef(1.f, 1.f + __expf(-a));
        int ob = node * 256 + tid * 4;
        out[ob + 0] = no_s[tid];
        #pragma unroll
        for (int m = 0; m < 3; m++)
            out[ob + 1 + m] = (hti[tid * 3 + m] + htu_s[tid * 3 + m]) * gate;
    }
}

extern "C" void kernel_launch(void* const* d_in, const int* in_sizes, int n_in,
                              void* d_out, int out_size)
{
    const float*         f0    = (const float*)d_in[0];
    const float*         f1    = (const float*)d_in[1];
    const float*         rd    = (const float*)d_in[2];
    const int*           nidx  = (const int*)d_in[3];
    const unsigned char* nmask = (const unsigned char*)d_in[4];
    const float* ln_g = (const float*)d_in[5];
    const float* ln_b = (const float*)d_in[6];
    const float* eW1  = (const float*)d_in[7];
    const float* eb1  = (const float*)d_in[8];
    const float* eW2  = (const float*)d_in[9];
    const float* eb2  = (const float*)d_in[10];
    const float* hW1  = (const float*)d_in[11];
    const float* hb1  = (const float*)d_in[12];
    const float* hW2  = (const float*)d_in[13];
    const float* hb2  = (const float*)d_in[14];
    const float* nW1  = (const float*)d_in[15];
    const float* nb1  = (const float*)d_in[16];
    const float* nW2  = (const float*)d_in[17];
    const float* nb2  = (const float*)d_in[18];
    const float* hns  = (const float*)d_in[19];
    const float* hnb  = (const float*)d_in[20];
    const float* gW   = (const float*)d_in[21];
    const float* gb   = (const float*)d_in[22];
    float* out = (float*)d_out;

    cudaFuncSetAttribute(fused_kernel, cudaFuncAttributeMaxDynamicSharedMemorySize,
                         SMEM_FLOATS * (int)sizeof(float));

    detect_mask_kernel<<<1, 1>>>((const unsigned int*)nmask);
    c01_kernel<<<(B_ * N_) / 128, 512>>>(f0, eW1, eb1);
    fused_kernel<<<B_ * N_, 512, SMEM_FLOATS * sizeof(float)>>>(
        f0, f1, rd, nidx, nmask, ln_g, ln_b, eW1, eW2, eb2, hW1, hb1, hW2, hb2,
        nW1, nb1, nW2, nb2, hns, hnb, gW, gb, out);
}

// round 13
// speedup vs baseline: 1.7014x; 1.1738x over previous
#include <cuda_runtime.h>
#include <math.h>

typedef unsigned long long u64;

// Problem constants
#define B_   2
#define N_   2048
#define K_   48
#define W_   48     // edge-tile width (all edges at once)
#define XS   50     // padded smem row stride (floats) -- bank-conflict-free
#define D0_  64
#define D1_  64
#define H_   64
#define EIN_ 193
#define E2_  386    // 2*EIN
#define H4_  256    // 4*H

__device__ int g_mask_mode;  // 0=uint8, 1=int32, 2=float32

// Per-node rank-0 tables for GEMM1:
//   g_c0[n][o] = eb1[o] + nodes[n] . eW1[0:64, o]    (i-role)
//   g_c1[n][o] =          nodes[n] . eW1[64:128, o]  (j-role)
__device__ float g_c0[B_ * N_ * E2_];   // 6.05 MB
__device__ float g_c1[B_ * N_ * E2_];   // 6.05 MB

__global__ void detect_mask_kernel(const unsigned int* __restrict__ w) {
    bool int_ok = true, flt_ok = true;
    #pragma unroll 8
    for (int i = 0; i < 64; i++) {
        unsigned int v = w[i];
        if (v != 0u && v != 1u) int_ok = false;
        if (v != 0u && v != 0x3F800000u) flt_ok = false;
    }
    g_mask_mode = int_ok ? 1 : (flt_ok ? 2 : 0);
}

// Precompute c0/c1 for all nodes. Grid 32 x 512: block handles 128 nodes.
__global__ __launch_bounds__(512) void c01_kernel(
    const float* __restrict__ f0, const float* __restrict__ eW1,
    const float* __restrict__ eb1)
{
    __shared__ float f0s[128 * 64];   // 32 KB
    const int n0 = blockIdx.x * 128;
    const int tid = threadIdx.x;
    for (int e = tid; e < 128 * 64; e += 512) f0s[e] = f0[n0 * 64 + e];
    __syncthreads();
    const int o = tid;
    if (o < E2_) {
        float b = eb1[o];
        for (int g = 0; g < 8; g++) {
            float c0a[16], c1a[16];
            #pragma unroll
            for (int nn = 0; nn < 16; nn++) { c0a[nn] = 0.f; c1a[nn] = 0.f; }
            const float* fg = f0s + g * 16 * 64;
            for (int d = 0; d < 64; d++) {
                float w0 = eW1[d * E2_ + o];
                float w1 = eW1[(64 + d) * E2_ + o];
                #pragma unroll
                for (int nn = 0; nn < 16; nn++) {
                    float f = fg[nn * 64 + d];
                    c0a[nn] += f * w0;
                    c1a[nn] += f * w1;
                }
            }
            #pragma unroll
            for (int nn = 0; nn < 16; nn++) {
                int n = n0 + g * 16 + nn;
                g_c0[(u64)n * E2_ + o] = c0a[nn] + b;
                g_c1[(u64)n * E2_ + o] = c1a[nn];
            }
        }
    }
}

__device__ __forceinline__ float siluf(float v) {
    return v * __fdividef(1.f, 1.f + __expf(-v));
}
__device__ __forceinline__ u64 dup2(float w) {
    u64 r; asm("mov.b64 %0, {%1, %1};" : "=l"(r) : "f"(w)); return r;
}
__device__ __forceinline__ void ffma2(u64 &d, u64 a, u64 b) {
    asm("fma.rn.f32x2 %0, %1, %2, %0;" : "+l"(d) : "l"(a), "l"(b));
}
__device__ __forceinline__ u64 addf2(u64 a, u64 b) {
    u64 r; asm("add.rn.f32x2 %0, %1, %2;" : "=l"(r) : "l"(a), "l"(b)); return r;
}
__device__ __forceinline__ float2 unpk(u64 v) {
    float2 f; asm("mov.b64 {%0, %1}, %2;" : "=f"(f.x), "=f"(f.y) : "l"(v)); return f;
}

// Shared memory layout (floats), width-48 tiles, stride 50.
// Aliases: htw -> x region (x dead after GEMM1/2 phase);
//          red -> h1 region (h1 dead after GEMM2 completes).
#define OFF_NI   0          // 64
#define OFF_HTI  64         // 192
#define OFF_HNS  256        // 64
#define OFF_HNB  320        // 64
#define OFF_MSK  384        // 48
#define OFF_IDX  432        // 48 ints
#define OFF_MI   480        // 64
#define OFF_HTU  544        // 192
#define OFF_NM   736        // 128
#define OFF_HB   864        // 128
#define OFF_NO   992        // 64
#define OFF_STAT 1056       // 2
#define OFF_C0   1058       // 386 (ends 1444)
#define OFF_X    1448       // 65*50 = 3250 (64 nrm rows + rel_dist row)
#define OFF_HTW  1448       // alias: 64*50 = 3200 <= 3250
#define OFF_H1   4698       // 194*50 = 9700 (o-tile buffer)
#define OFF_RED  4698       // alias: 1536
#define OFF_M    14398      // 64*50 = 3200
#define OFF_H3   17598      // 128*50 = 6400 (g-tile buffer)
#define SMEM_FLOATS 23998   // 95,992 bytes -> 2 blocks/SM

__global__ __launch_bounds__(512, 2) void fused_kernel(
    const float* __restrict__ f0, const float* __restrict__ f1,
    const float* __restrict__ rd, const int* __restrict__ nidx,
    const unsigned char* __restrict__ nmask,
    const float* __restrict__ ln_g, const float* __restrict__ ln_b,
    const float* __restrict__ eW1,
    const float* __restrict__ eW2, const float* __restrict__ eb2,
    const float* __restrict__ hW1, const float* __restrict__ hb1,
    const float* __restrict__ hW2, const float* __restrict__ hb2,
    const float* __restrict__ nW1, const float* __restrict__ nb1,
    const float* __restrict__ nW2, const float* __restrict__ nb2,
    const float* __restrict__ hns, const float* __restrict__ hnb,
    const float* __restrict__ gW, const float* __restrict__ gb,
    float* __restrict__ out)
{
    extern __shared__ float sm[];
    const int node = blockIdx.x;
    const int base = (node >> 11) << 11;
    const int tid = threadIdx.x;

    float* ni_s  = sm + OFF_NI;
    float* hti   = sm + OFF_HTI;
    float* hns_s = sm + OFF_HNS;
    float* hnb_s = sm + OFF_HNB;
    float* msk_s = sm + OFF_MSK;
    int*   idx_s = (int*)(sm + OFF_IDX);
    float* mi_s  = sm + OFF_MI;
    float* htu_s = sm + OFF_HTU;
    float* nm    = sm + OFF_NM;
    float* hbuf  = sm + OFF_HB;
    float* no_s  = sm + OFF_NO;
    float* stat  = sm + OFF_STAT;
    float* c0_s  = sm + OFF_C0;
    float* x_s   = sm + OFF_X;
    float* htw_s = sm + OFF_HTW;
    float* h1_s  = sm + OFF_H1;
    float* red   = sm + OFF_RED;
    float* m_s   = sm + OFF_M;
    float* h3_s  = sm + OFF_H3;

    // ---- Stage 0: per-node loads ----
    if (tid < 64) {
        ni_s[tid]  = f0[node * 64 + tid];
        hns_s[tid] = hns[tid];
        hnb_s[tid] = hnb[tid];
    }
    if (tid >= 64 && tid < 256) hti[tid - 64] = f1[node * 192 + (tid - 64)];
    if (tid >= 256 && tid < 304) {
        int k = tid - 256;
        idx_s[k] = nidx[node * 48 + k];
        int mode = g_mask_mode;
        float mv;
        if (mode == 1)      mv = ((const int*)nmask)[node * 48 + k] ? 1.f : 0.f;
        else if (mode == 2) mv = ((const float*)nmask)[node * 48 + k];
        else                mv = nmask[node * 48 + k] ? 1.f : 0.f;
        msk_s[k] = mv;
    }
    if (tid < E2_) c0_s[tid] = g_c0[(u64)node * E2_ + tid];
    __syncthreads();

    // ---- Stage 1: build x rows (rel_ht_dist 64 rows + rel_dist row), all 48 k ----
    for (int e = tid; e < 48 * 64; e += 512) {
        int k = e >> 6, d = e & 63;
        int j = base + idx_s[k];
        const float* hj = f1 + j * 192 + d * 3;
        float r0 = hti[d * 3 + 0] - hj[0];
        float r1 = hti[d * 3 + 1] - hj[1];
        float r2 = hti[d * 3 + 2] - hj[2];
        x_s[d * XS + k] = sqrtf(r0 * r0 + r1 * r1 + r2 * r2);
    }
    if (tid < 48) x_s[64 * XS + tid] = rd[node * 48 + tid];
    __syncthreads();

    const int ob  = tid & 63;          // output lane (64-wide)
    const int kg6 = (tid >> 6) * 6;    // 8 k-groups x 6 k

    // ==== Fused GEMM1 -> GEMM2 over o-tiles {0:192, 192:386} ====
    u64 macc0 = 0, macc1 = 0, macc2 = 0;   // GEMM2 accumulators (h=ob, k=kg6..+5)
    #pragma unroll 1
    for (int t = 0; t < 2; t++) {
        const int obase = t * 192;
        // --- GEMM1 tile: h1[ol][k] = c0[o] + sum_i x[i][k]*eW1[128+i][o] (+c1_j, silu) ---
        {
            u64 acc[3][3];
            #pragma unroll
            for (int oi = 0; oi < 3; oi++) {
                u64 dd = dup2(c0_s[obase + ob + 64 * oi]);
                acc[oi][0] = dd; acc[oi][1] = dd; acc[oi][2] = dd;
            }
            const float* xb = x_s + kg6;
            const float* wcol = eW1 + 128 * E2_ + obase + ob;
            float wn0 = wcol[0], wn1 = wcol[64], wn2 = wcol[128];
            for (int i = 0; i < 65; i++) {
                float w0 = wn0, w1 = wn1, w2 = wn2;
                if (i < 64) {
                    const float* wr = wcol + (i + 1) * E2_;
                    wn0 = wr[0]; wn1 = wr[64]; wn2 = wr[128];
                }
                const u64* xr = (const u64*)(xb + i * XS);
                u64 a0 = xr[0], a1 = xr[1], a2 = xr[2];
                u64 wp;
                wp = dup2(w0); ffma2(acc[0][0], a0, wp); ffma2(acc[0][1], a1, wp); ffma2(acc[0][2], a2, wp);
                wp = dup2(w1); ffma2(acc[1][0], a0, wp); ffma2(acc[1][1], a1, wp); ffma2(acc[1][2], a2, wp);
                wp = dup2(w2); ffma2(acc[2][0], a0, wp); ffma2(acc[2][1], a1, wp); ffma2(acc[2][2], a2, wp);
            }
            // epilogue: add gathered c1_j, silu, store tile rows (local 0..191)
            const float* c1p[6];
            #pragma unroll
            for (int jj = 0; jj < 6; jj++)
                c1p[jj] = g_c1 + (u64)(base + idx_s[kg6 + jj]) * E2_ + obase + ob;
            #pragma unroll
            for (int oi = 0; oi < 3; oi++) {
                float* dst = h1_s + (ob + 64 * oi) * XS + kg6;
                #pragma unroll
                for (int j2 = 0; j2 < 3; j2++) {
                    float2 p = unpk(acc[oi][j2]);
                    p.x = siluf(p.x + c1p[2 * j2][64 * oi]);
                    p.y = siluf(p.y + c1p[2 * j2 + 1][64 * oi]);
                    *(float2*)(dst + 2 * j2) = p;
                }
            }
        }
        // --- mini-pass: o = 384, 385 -> tile-1 local rows 192, 193 ---
        if (t == 1 && tid < 96) {
            int o = 384 + (tid & 1);
            int k = tid >> 1;
            float a = c0_s[o];
            const float* wc = eW1 + 128 * E2_ + o;
            for (int i = 0; i < 65; i++) a += x_s[i * XS + k] * wc[i * E2_];
            a += g_c1[(u64)(base + idx_s[k]) * E2_ + o];
            h1_s[(192 + (o - 384)) * XS + k] = siluf(a);
        }
        __syncthreads();
        // --- GEMM2 accumulate this tile (h1 reads are warp-broadcast) ---
        {
            const int R = t ? 194 : 192;
            const float* wc = eW2 + obase * 64 + ob;
            for (int ol = 0; ol < R; ol++) {
                const u64* hp = (const u64*)(h1_s + ol * XS + kg6);
                u64 a0 = hp[0], a1 = hp[1], a2 = hp[2];
                u64 wp = dup2(wc[ol * 64]);
                ffma2(macc0, a0, wp); ffma2(macc1, a1, wp); ffma2(macc2, a2, wp);
            }
        }
        __syncthreads();
    }
    // ---- GEMM2 epilogue: m[h][k] = silu(acc + eb2[h]) ----
    {
        u64 bp = dup2(eb2[ob]);
        u64 t0 = addf2(macc0, bp), t1 = addf2(macc1, bp), t2 = addf2(macc2, bp);
        float* dst = m_s + ob * XS + kg6;
        float2 p;
        p = unpk(t0); *(float2*)(dst + 0) = make_float2(siluf(p.x), siluf(p.y));
        p = unpk(t1); *(float2*)(dst + 2) = make_float2(siluf(p.x), siluf(p.y));
        p = unpk(t2); *(float2*)(dst + 4) = make_float2(siluf(p.x), siluf(p.y));
    }
    __syncthreads();

    // ---- m_i partials (masked sum over k) -> red (aliases dead h1) ----
    {
        float s = 0.f;
        #pragma unroll
        for (int kk = 0; kk < 6; kk++) s += msk_s[kg6 + kk] * m_s[ob * XS + kg6 + kk];
        red[(tid >> 6) * 64 + ob] = s;
    }
    __syncthreads();
    if (tid < 64) {
        float s = 0.f;
        #pragma unroll
        for (int kb = 0; kb < 8; kb++) s += red[kb * 64 + tid];
        mi_s[tid] = s;
    }

    // ==== Fused GEMM3 -> GEMM4 over g-tiles {0:128, 128:256} ====
    u64 wacc0 = 0, wacc1 = 0, wacc2 = 0;   // GEMM4 accumulators (d=ob, k=kg6..+5)
    #pragma unroll 1
    for (int t = 0; t < 2; t++) {
        const int gbase = t * 128;
        // --- GEMM3 tile: h3[gl][k] = silu(hb1[g] + sum_h m[h][k]*hW1[h][g]) ---
        {
            u64 acc[2][3];
            {
                u64 d0v = dup2(hb1[gbase + ob]);
                u64 d1v = dup2(hb1[gbase + ob + 64]);
                acc[0][0] = d0v; acc[0][1] = d0v; acc[0][2] = d0v;
                acc[1][0] = d1v; acc[1][1] = d1v; acc[1][2] = d1v;
            }
            const float* wc = hW1 + gbase + ob;
            for (int h = 0; h < 64; h++) {
                const u64* mp = (const u64*)(m_s + h * XS + kg6);
                u64 a0 = mp[0], a1 = mp[1], a2 = mp[2];
                const float* wr = wc + h * H4_;
                u64 w0 = dup2(wr[0]), w1 = dup2(wr[64]);
                ffma2(acc[0][0], a0, w0); ffma2(acc[0][1], a1, w0); ffma2(acc[0][2], a2, w0);
                ffma2(acc[1][0], a0, w1); ffma2(acc[1][1], a1, w1); ffma2(acc[1][2], a2, w1);
            }
            #pragma unroll
            for (int oi = 0; oi < 2; oi++) {
                float* dst = h3_s + (ob + 64 * oi) * XS + kg6;
                #pragma unroll
                for (int j2 = 0; j2 < 3; j2++) {
                    float2 p = unpk(acc[oi][j2]);
                    *(float2*)(dst + 2 * j2) = make_float2(siluf(p.x), siluf(p.y));
                }
            }
        }
        __syncthreads();
        // --- GEMM4 accumulate this tile ---
        {
            const float* wc = hW2 + gbase * 64 + ob;
            for (int gl = 0; gl < 128; gl++) {
                const u64* hp = (const u64*)(h3_s + gl * XS + kg6);
                u64 a0 = hp[0], a1 = hp[1], a2 = hp[2];
                u64 wp = dup2(wc[gl * 64]);
                ffma2(wacc0, a0, wp); ffma2(wacc1, a1, wp); ffma2(wacc2, a2, wp);
            }
        }
        __syncthreads();
    }
    // ---- GEMM4 epilogue: htw[d][k] = acc + hb2[d]  (htw aliases dead x) ----
    {
        u64 bp = dup2(hb2[ob]);
        u64 t0 = addf2(wacc0, bp), t1 = addf2(wacc1, bp), t2 = addf2(wacc2, bp);
        float* dst = htw_s + ob * XS + kg6;
        *(u64*)(dst + 0) = t0; *(u64*)(dst + 2) = t1; *(u64*)(dst + 4) = t2;
    }
    __syncthreads();

    // ---- ht_update einsum ----
    {
        const int d = ob;
        const int kb = tid >> 6;
        float a0 = 0.f, a1 = 0.f, a2 = 0.f;
        float sc = hns_s[d], bi = hnb_s[d];
        float h0 = hti[d * 3 + 0], h1v = hti[d * 3 + 1], h2 = hti[d * 3 + 2];
        #pragma unroll
        for (int kk = 0; kk < 6; kk++) {
            int k = kg6 + kk;
            int j = base + idx_s[k];
            const float* hj = f1 + j * 192 + d * 3;
            float r0 = h0 - hj[0];
            float r1 = h1v - hj[1];
            float r2 = h2 - hj[2];
            float nrm = sqrtf(r0 * r0 + r1 * r1 + r2 * r2);
            float coef = (nrm * sc + bi) / fmaxf(nrm, 1e-8f);
            float w = coef * htw_s[d * XS + k];
            a0 += r0 * w; a1 += r1 * w; a2 += r2 * w;
        }
        red[kb * 192 + d * 3 + 0] = a0;
        red[kb * 192 + d * 3 + 1] = a1;
        red[kb * 192 + d * 3 + 2] = a2;
    }
    __syncthreads();
    if (tid < 192) {
        float s = 0.f;
        #pragma unroll
        for (int kb = 0; kb < 8; kb++) s += red[kb * 192 + tid];
        htu_s[tid] = s;
    }
    __syncthreads();

    // ---- Node tail: LayerNorm -> MLP(128->128->64) + residual -> gate -> output ----
    if (tid < 32) {
        float s = ni_s[tid] + ni_s[tid + 32];
        #pragma unroll
        for (int off = 16; off > 0; off >>= 1) s += __shfl_xor_sync(0xffffffffu, s, off);
        if (tid == 0) stat[0] = s * (1.f / 64.f);
    }
    __syncthreads();
    if (tid < 32) {
        float mu = stat[0];
        float d0 = ni_s[tid] - mu, d1 = ni_s[tid + 32] - mu;
        float s = d0 * d0 + d1 * d1;
        #pragma unroll
        for (int off = 16; off > 0; off >>= 1) s += __shfl_xor_sync(0xffffffffu, s, off);
        if (tid == 0) stat[1] = s * (1.f / 64.f);
    }
    __syncthreads();
    if (tid < 64) {
        float mu = stat[0];
        float inv = rsqrtf(stat[1] + 1e-5f);
        nm[tid] = (ni_s[tid] - mu) * inv * ln_g[tid] + ln_b[tid];
        nm[64 + tid] = mi_s[tid];
    }
    __syncthreads();
    if (tid < 128) {
        float a = nb1[tid];
        #pragma unroll 8
        for (int e = 0; e < 128; e++) a += nm[e] * nW1[e * 128 + tid];
        hbuf[tid] = siluf(a);
    }
    __syncthreads();
    if (tid < 64) {
        float a = nb2[tid];
        #pragma unroll 8
        for (int g = 0; g < 128; g++) a += hbuf[g] * nW2[g * 64 + tid];
        no_s[tid] = a + ni_s[tid];
    }
    __syncthreads();
    if (tid < 64) {
        float a = gb[tid];
        #pragma unroll 8
        for (int e = 0; e < 64; e++) a += no_s[e] * gW[e * 64 + tid];
        float gate = __fdividef(1.f, 1.f + __expf(-a));
        int obp = node * 256 + tid * 4;
        out[obp + 0] = no_s[tid];
        #pragma unroll
        for (int m = 0; m < 3; m++)
            out[obp + 1 + m] = (hti[tid * 3 + m] + htu_s[tid * 3 + m]) * gate;
    }
}

extern "C" void kernel_launch(void* const* d_in, const int* in_sizes, int n_in,
                              void* d_out, int out_size)
{
    const float*         f0    = (const float*)d_in[0];
    const float*         f1    = (const float*)d_in[1];
    const float*         rd    = (const float*)d_in[2];
    const int*           nidx  = (const int*)d_in[3];
    const unsigned char* nmask = (const unsigned char*)d_in[4];
    const float* ln_g = (const float*)d_in[5];
    const float* ln_b = (const float*)d_in[6];
    const float* eW1  = (const float*)d_in[7];
    const float* eb1  = (const float*)d_in[8];
    const float* eW2  = (const float*)d_in[9];
    const float* eb2  = (const float*)d_in[10];
    const float* hW1  = (const float*)d_in[11];
    const float* hb1  = (const float*)d_in[12];
    const float* hW2  = (const float*)d_in[13];
    const float* hb2  = (const float*)d_in[14];
    const float* nW1  = (const float*)d_in[15];
    const float* nb1  = (const float*)d_in[16];
    const float* nW2  = (const float*)d_in[17];
    const float* nb2  = (const float*)d_in[18];
    const float* hns  = (const float*)d_in[19];
    const float* hnb  = (const float*)d_in[20];
    const float* gW   = (const float*)d_in[21];
    const float* gb   = (const float*)d_in[22];
    float* out = (float*)d_out;

    cudaFuncSetAttribute(fused_kernel, cudaFuncAttributeMaxDynamicSharedMemorySize,
                         SMEM_FLOATS * (int)sizeof(float));

    detect_mask_kernel<<<1, 1>>>((const unsigned int*)nmask);
    c01_kernel<<<(B_ * N_) / 128, 512>>>(f0, eW1, eb1);
    fused_kernel<<<B_ * N_, 512, SMEM_FLOATS * sizeof(float)>>>(
        f0, f1, rd, nidx, nmask, ln_g, ln_b, eW1, eW2, eb2, hW1, hb1, hW2, hb2,
        nW1, nb1, nW2, nb2, hns, hnb, gW, gb, out);
}